// round 2
// baseline (speedup 1.0000x reference)
#include <cuda_runtime.h>
#include <cuda_bf16.h>

#define LEN_Q   13294
#define NQ      (2 * LEN_Q)     // 26588 rows (b*LEN_Q + q)
#define N_OUT   384             // 256 offset cols + 128 attn cols

// Scratch: projection output P[NQ][384]
__device__ float g_P[NQ * N_OUT];

// ---------------------------------------------------------------------------
// GEMM: P = Q @ [W_off | W_attn] + [b_off | b_attn]
// BM=64, BN=128, BK=16, 256 threads, 8x4 micro-tile per thread.
// grid = (ceil(NQ/64), 3): blockIdx.y 0,1 -> W_off cols 0..255; 2 -> W_attn.
// ---------------------------------------------------------------------------
__global__ __launch_bounds__(256) void msda_gemm_kernel(
    const float* __restrict__ Q,
    const float* __restrict__ Woff, const float* __restrict__ boff,
    const float* __restrict__ Wattn, const float* __restrict__ battn)
{
    __shared__ float Qs[64][16];
    __shared__ float Ws[16][128];

    const int m0   = blockIdx.x * 64;
    const int nblk = blockIdx.y;

    const float* W;
    const float* bias;
    int ldW, n0;
    if (nblk < 2) { W = Woff;  bias = boff + nblk * 128; ldW = 256; n0 = nblk * 128; }
    else          { W = Wattn; bias = battn;             ldW = 128; n0 = 0;          }
    const int outn0 = nblk * 128;

    const int tid = threadIdx.x;
    const int tx  = tid & 31;      // col group
    const int ty  = tid >> 5;      // row group (warp id)

    // global-load index mapping
    const int qr = tid >> 2;            // 0..63  (Q tile row)
    const int qc = (tid & 3) * 4;       // 0,4,8,12 (Q tile col, float4)
    const int wr = tid >> 4;            // 0..15  (W tile row)
    const int wc = (tid & 15) * 8;      // 0..120 (W tile col, 2x float4)

    float acc[8][4];
#pragma unroll
    for (int i = 0; i < 8; i++)
#pragma unroll
        for (int j = 0; j < 4; j++) acc[i][j] = 0.f;

#pragma unroll 1
    for (int k0 = 0; k0 < 256; k0 += 16) {
        // stage global -> regs
        float4 qv = make_float4(0.f, 0.f, 0.f, 0.f);
        if (m0 + qr < NQ)
            qv = *(const float4*)&Q[(size_t)(m0 + qr) * 256 + k0 + qc];
        float4 w0 = *(const float4*)&W[(size_t)(k0 + wr) * ldW + n0 + wc];
        float4 w1 = *(const float4*)&W[(size_t)(k0 + wr) * ldW + n0 + wc + 4];

        __syncthreads();
        Qs[qr][qc + 0] = qv.x; Qs[qr][qc + 1] = qv.y;
        Qs[qr][qc + 2] = qv.z; Qs[qr][qc + 3] = qv.w;
        *(float4*)&Ws[wr][wc]     = w0;
        *(float4*)&Ws[wr][wc + 4] = w1;
        __syncthreads();

#pragma unroll
        for (int k = 0; k < 16; k++) {
            float a[8];
#pragma unroll
            for (int i = 0; i < 8; i++) a[i] = Qs[ty * 8 + i][k];
            float4 bv = *(const float4*)&Ws[k][tx * 4];
            float bb[4] = {bv.x, bv.y, bv.z, bv.w};
#pragma unroll
            for (int i = 0; i < 8; i++)
#pragma unroll
                for (int j = 0; j < 4; j++)
                    acc[i][j] = fmaf(a[i], bb[j], acc[i][j]);
        }
    }

    // epilogue: add bias, store
    const float4 bq = *(const float4*)&bias[tx * 4];
#pragma unroll
    for (int i = 0; i < 8; i++) {
        const int m = m0 + ty * 8 + i;
        if (m < NQ) {
            float4 o;
            o.x = acc[i][0] + bq.x;
            o.y = acc[i][1] + bq.y;
            o.z = acc[i][2] + bq.z;
            o.w = acc[i][3] + bq.w;
            *(float4*)&g_P[(size_t)m * N_OUT + outn0 + tx * 4] = o;
        }
    }
}

// ---------------------------------------------------------------------------
// Sampling: one warp per (b, q, head). lane = channel within head (D_HEAD=32).
// Lanes 0..15 own point j (lanes 16..31 mirror): softmax + location, then
// broadcast each of the 16 samples via shfl and gather 4 corners per lane.
// ---------------------------------------------------------------------------
__global__ __launch_bounds__(256) void msda_sample_kernel(
    const float* __restrict__ ref,    // (2, LEN_Q, 4, 2)
    const float* __restrict__ value,  // (2, LEN_Q, 256)
    float* __restrict__ out)          // (2, LEN_Q, 256)
{
    const int gw = (blockIdx.x * 256 + threadIdx.x) >> 5;   // global warp id
    const int lane = threadIdx.x & 31;
    const int h   = gw & 7;
    const int row = gw >> 3;              // b*LEN_Q + q
    const int b   = (row >= LEN_Q) ? 1 : 0;

    const int j = lane & 15;              // point index (l*4+p)
    const int l = j >> 2;

    const float* Prow = g_P + (size_t)row * N_OUT;
    const float offx  = Prow[h * 32 + j * 2];
    const float offy  = Prow[h * 32 + j * 2 + 1];
    const float logit = Prow[256 + h * 16 + j];

    // softmax over 16 points (halves of the warp hold identical copies)
    float mx = logit;
#pragma unroll
    for (int s = 8; s; s >>= 1) mx = fmaxf(mx, __shfl_xor_sync(0xffffffffu, mx, s));
    const float e = __expf(logit - mx);
    float ssum = e;
#pragma unroll
    for (int s = 8; s; s >>= 1) ssum += __shfl_xor_sync(0xffffffffu, ssum, s);
    const float wgt = e / ssum;

    // sample location in pixel space: x = ref*W + off - 0.5  (levels are square)
    const float dim = (l == 0) ? 100.f : (l == 1) ? 50.f : (l == 2) ? 25.f : 13.f;
    const float rx = ref[(size_t)(row * 4 + l) * 2 + 0];
    const float ry = ref[(size_t)(row * 4 + l) * 2 + 1];
    const float x = fmaf(rx, dim, offx) - 0.5f;
    const float y = fmaf(ry, dim, offy) - 0.5f;

    float acc = 0.f;
    const float* vb = value + (size_t)b * LEN_Q * 256 + h * 32 + lane;

#pragma unroll
    for (int jj = 0; jj < 16; jj++) {
        const float xs = __shfl_sync(0xffffffffu, x,   jj);
        const float ys = __shfl_sync(0xffffffffu, y,   jj);
        const float ws = __shfl_sync(0xffffffffu, wgt, jj);
        const int ll   = jj >> 2;                         // compile-time (unrolled)
        const int D    = (ll == 0) ? 100 : (ll == 1) ? 50 : (ll == 2) ? 25 : 13;
        const int BASE = (ll == 0) ? 0 : (ll == 1) ? 10000 : (ll == 2) ? 12500 : 13125;

        const float xf = floorf(xs), yf = floorf(ys);
        const int x0 = (int)xf, y0 = (int)yf;
        const float fx = xs - xf, fy = ys - yf;

        const bool vx0 = (x0 >= 0)     && (x0 < D);
        const bool vx1 = (x0 + 1 >= 0) && (x0 + 1 < D);
        const bool vy0 = (y0 >= 0)     && (y0 < D);
        const bool vy1 = (y0 + 1 >= 0) && (y0 + 1 < D);

        const float* rb = vb + (size_t)BASE * 256;
        const long long i00 = ((long long)y0 * D + x0) * 256;

        const float v00 = (vx0 && vy0) ? rb[i00]               : 0.f;
        const float v01 = (vx1 && vy0) ? rb[i00 + 256]         : 0.f;
        const float v10 = (vx0 && vy1) ? rb[i00 + D * 256]     : 0.f;
        const float v11 = (vx1 && vy1) ? rb[i00 + D * 256 + 256] : 0.f;

        const float top = v00 + fx * (v01 - v00);
        const float bot = v10 + fx * (v11 - v10);
        acc = fmaf(ws, top + fy * (bot - top), acc);
    }

    out[(size_t)row * 256 + h * 32 + lane] = acc;
}

// ---------------------------------------------------------------------------
extern "C" void kernel_launch(void* const* d_in, const int* in_sizes, int n_in,
                              void* d_out, int out_size)
{
    const float* query = (const float*)d_in[0];   // (2, LEN_Q, 256)
    const float* ref   = (const float*)d_in[1];   // (2, LEN_Q, 4, 2)
    const float* value = (const float*)d_in[2];   // (2, LEN_Q, 256)
    const float* Woff  = (const float*)d_in[3];   // (256, 256)
    const float* boff  = (const float*)d_in[4];   // (256,)
    const float* Wattn = (const float*)d_in[5];   // (256, 128)
    const float* battn = (const float*)d_in[6];   // (128,)
    float* out = (float*)d_out;                   // (2, LEN_Q, 256)

    dim3 ggrid((NQ + 63) / 64, 3);
    msda_gemm_kernel<<<ggrid, 256>>>(query, Woff, boff, Wattn, battn);

    const int nwarps  = NQ * 8;                   // one warp per (b,q,head)
    const int nblocks = (nwarps * 32 + 255) / 256;
    msda_sample_kernel<<<nblocks, 256>>>(ref, value, out);
}

// round 3
// speedup vs baseline: 1.1284x; 1.1284x over previous
#include <cuda_runtime.h>
#include <cuda_bf16.h>

#define LEN_Q   13294
#define NQ      (2 * LEN_Q)     // 26588 rows (b*LEN_Q + q)
#define N_OUT   384             // 256 offset cols + 128 attn cols

typedef unsigned long long ull;

// Scratch: projection output P[NQ][384]
__device__ float g_P[NQ * N_OUT];

// ---- packed f32x2 helpers (Blackwell) -------------------------------------
__device__ __forceinline__ void fma2(ull& d, ull a, ull b) {
    asm("fma.rn.f32x2 %0, %1, %2, %0;" : "+l"(d) : "l"(a), "l"(b));
}
__device__ __forceinline__ ull pack2(float lo, float hi) {
    ull r; asm("mov.b64 %0, {%1, %2};" : "=l"(r) : "f"(lo), "f"(hi)); return r;
}
__device__ __forceinline__ void unpack2(ull v, float& lo, float& hi) {
    asm("mov.b64 {%0, %1}, %2;" : "=f"(lo), "=f"(hi) : "l"(v));
}

// ---------------------------------------------------------------------------
// GEMM: P = Q @ [W_off | W_attn] + bias.  BM=128, BN=128, BK=16, 256 threads,
// 8x8 micro-tile per thread with fma.rn.f32x2 (double-rate fp32).
// grid = (ceil(NQ/128), 3): y 0,1 -> W_off halves; 2 -> W_attn.
// ---------------------------------------------------------------------------
__global__ __launch_bounds__(256) void msda_gemm_kernel(
    const float* __restrict__ Q,
    const float* __restrict__ Woff, const float* __restrict__ boff,
    const float* __restrict__ Wattn, const float* __restrict__ battn)
{
    __shared__ float As[16][136];   // [k][m], padded row
    __shared__ float Bs[16][128];   // [k][n]

    const int m0   = blockIdx.x * 128;
    const int nblk = blockIdx.y;

    const float* W; const float* bias; int ldW, n0;
    if (nblk < 2) { W = Woff;  bias = boff + nblk * 128; ldW = 256; n0 = nblk * 128; }
    else          { W = Wattn; bias = battn;             ldW = 128; n0 = 0;          }
    const int outn0 = nblk * 128;

    const int tid = threadIdx.x;
    const int tx  = tid & 15;       // col octet: cols tx*8 .. tx*8+7
    const int ty  = tid >> 4;       // row octet: rows ty*8 .. ty*8+7

    const int ar = tid >> 1;        // 0..127 (A tile row)
    const int ac = (tid & 1) * 8;   // 0/8    (A tile k, 2x float4)
    const int br = tid >> 4;        // 0..15  (B tile row)
    const int bc = (tid & 15) * 8;  // B tile col, 2x float4

    ull acc2[8][4];
#pragma unroll
    for (int i = 0; i < 8; i++)
#pragma unroll
        for (int jp = 0; jp < 4; jp++) acc2[i][jp] = 0ull;

#pragma unroll 1
    for (int k0 = 0; k0 < 256; k0 += 16) {
        float4 a0 = make_float4(0.f,0.f,0.f,0.f), a1 = a0;
        if (m0 + ar < NQ) {
            const float* qp = &Q[(size_t)(m0 + ar) * 256 + k0 + ac];
            a0 = *(const float4*)qp;
            a1 = *(const float4*)(qp + 4);
        }
        const float* wp = &W[(size_t)(k0 + br) * ldW + n0 + bc];
        float4 b0 = *(const float4*)wp;
        float4 b1 = *(const float4*)(wp + 4);

        __syncthreads();
        As[ac + 0][ar] = a0.x; As[ac + 1][ar] = a0.y;
        As[ac + 2][ar] = a0.z; As[ac + 3][ar] = a0.w;
        As[ac + 4][ar] = a1.x; As[ac + 5][ar] = a1.y;
        As[ac + 6][ar] = a1.z; As[ac + 7][ar] = a1.w;
        *(float4*)&Bs[br][bc]     = b0;
        *(float4*)&Bs[br][bc + 4] = b1;
        __syncthreads();

#pragma unroll
        for (int k = 0; k < 16; k++) {
            float4 av0 = *(const float4*)&As[k][ty * 8];
            float4 av1 = *(const float4*)&As[k][ty * 8 + 4];
            longlong2 bv0 = *(const longlong2*)&Bs[k][tx * 8];
            longlong2 bv1 = *(const longlong2*)&Bs[k][tx * 8 + 4];
            ull bb[4] = { (ull)bv0.x, (ull)bv0.y, (ull)bv1.x, (ull)bv1.y };
            float aa[8] = { av0.x, av0.y, av0.z, av0.w,
                            av1.x, av1.y, av1.z, av1.w };
#pragma unroll
            for (int i = 0; i < 8; i++) {
                ull ad = pack2(aa[i], aa[i]);
#pragma unroll
                for (int jp = 0; jp < 4; jp++) fma2(acc2[i][jp], ad, bb[jp]);
            }
        }
    }

    const float4 bq0 = *(const float4*)&bias[tx * 8];
    const float4 bq1 = *(const float4*)&bias[tx * 8 + 4];
    const float bcol[8] = { bq0.x, bq0.y, bq0.z, bq0.w,
                            bq1.x, bq1.y, bq1.z, bq1.w };

#pragma unroll
    for (int i = 0; i < 8; i++) {
        const int m = m0 + ty * 8 + i;
        if (m < NQ) {
            float o[8];
#pragma unroll
            for (int jp = 0; jp < 4; jp++) unpack2(acc2[i][jp], o[jp*2], o[jp*2+1]);
            float4 s0 = make_float4(o[0]+bcol[0], o[1]+bcol[1], o[2]+bcol[2], o[3]+bcol[3]);
            float4 s1 = make_float4(o[4]+bcol[4], o[5]+bcol[5], o[6]+bcol[6], o[7]+bcol[7]);
            float* gp = &g_P[(size_t)m * N_OUT + outn0 + tx * 8];
            *(float4*)gp       = s0;
            *(float4*)(gp + 4) = s1;
        }
    }
}

// ---------------------------------------------------------------------------
// Sampling v2: one warp per (b, q, head), lane = channel (D_HEAD=32).
// Lanes 0..15 (mirrored in 16..31) precompute, per point j:
//   - softmax weight, pixel coords, per-corner weights with validity folded in
//   - a single clamped flat index such that the 4 fixed-offset loads are both
//     in-bounds AND texel-correct for every nonzero-weight corner.
// Inner loop per point: 5 SHFL + 1 addr IMAD + 4 LDG + 4 FMA.
// ---------------------------------------------------------------------------
__global__ __launch_bounds__(256) void msda_sample_kernel(
    const float* __restrict__ ref,    // (2, LEN_Q, 4, 2)
    const float* __restrict__ value,  // (2, LEN_Q, 256)
    float* __restrict__ out)          // (2, LEN_Q, 256)
{
    const int gw   = (blockIdx.x * 256 + threadIdx.x) >> 5;
    const int lane = threadIdx.x & 31;
    const int h    = gw & 7;
    const int row  = gw >> 3;              // b*LEN_Q + q
    const int b    = (row >= LEN_Q) ? 1 : 0;

    const int j = lane & 15;               // point index (l*4+p)
    const int l = j >> 2;

    const float* Prow = g_P + (size_t)row * N_OUT;
    const float offx  = Prow[h * 32 + j * 2];
    const float offy  = Prow[h * 32 + j * 2 + 1];
    const float logit = Prow[256 + h * 16 + j];

    // softmax over 16 points (warp halves hold identical copies)
    float mx = logit;
#pragma unroll
    for (int s = 8; s; s >>= 1) mx = fmaxf(mx, __shfl_xor_sync(0xffffffffu, mx, s));
    const float e = __expf(logit - mx);
    float ssum = e;
#pragma unroll
    for (int s = 8; s; s >>= 1) ssum += __shfl_xor_sync(0xffffffffu, ssum, s);
    const float wgt = e / ssum;

    const int   D   = (l == 0) ? 100 : (l == 1) ? 50 : (l == 2) ? 25 : 13;
    const float dim = (float)D;
    const float rx = ref[(size_t)(row * 4 + l) * 2 + 0];
    const float ry = ref[(size_t)(row * 4 + l) * 2 + 1];
    const float x = fmaf(rx, dim, offx) - 0.5f;
    const float y = fmaf(ry, dim, offy) - 0.5f;

    const float xf = floorf(x), yf = floorf(y);
    const int x0 = (int)xf, y0 = (int)yf;
    const float fx = x - xf, fy = y - yf;

    // axis weights with validity folded in
    const float gx0 = (x0 >= 0     && x0 < D)     ? (1.f - fx) : 0.f;
    const float gx1 = (x0 + 1 >= 0 && x0 + 1 < D) ? fx         : 0.f;
    const float gy0 = (y0 >= 0     && y0 < D)     ? (1.f - fy) : 0.f;
    const float gy1 = (y0 + 1 >= 0 && y0 + 1 < D) ? fy         : 0.f;

    // clamp each axis to [0, D-2]; remap weights so the clamped 2x2 window
    // assigns each valid corner its weight at the correct texel.
    const int cx = min(max(x0, 0), D - 2);
    const int cy = min(max(y0, 0), D - 2);
    const float wl = (x0 < 0) ? gx1 : ((x0 <= D - 2) ? gx0 : 0.f);
    const float wr = (x0 < 0) ? 0.f : ((x0 <= D - 2) ? gx1 : gx0);
    const float wt = (y0 < 0) ? gy1 : ((y0 <= D - 2) ? gy0 : 0.f);
    const float wb = (y0 < 0) ? 0.f : ((y0 <= D - 2) ? gy1 : gy0);

    const float w00 = wgt * wl * wt;
    const float w01 = wgt * wr * wt;
    const float w10 = wgt * wl * wb;
    const float w11 = wgt * wr * wb;
    const int flat = cy * D + cx;          // all 4 corners in-bounds

    float acc = 0.f;
    const float* vb = value + (size_t)b * LEN_Q * 256 + h * 32 + lane;

#pragma unroll
    for (int jj = 0; jj < 16; jj++) {
        const int   idx = __shfl_sync(0xffffffffu, flat, jj);
        const float s00 = __shfl_sync(0xffffffffu, w00,  jj);
        const float s01 = __shfl_sync(0xffffffffu, w01,  jj);
        const float s10 = __shfl_sync(0xffffffffu, w10,  jj);
        const float s11 = __shfl_sync(0xffffffffu, w11,  jj);
        const int ll   = jj >> 2;                        // compile-time (unrolled)
        const int DD   = (ll == 0) ? 100 : (ll == 1) ? 50 : (ll == 2) ? 25 : 13;
        const int BASE = (ll == 0) ? 0 : (ll == 1) ? 10000 : (ll == 2) ? 12500 : 13125;

        const float* p = vb + (size_t)BASE * 256 + (size_t)idx * 256;
        acc = fmaf(s00, p[0],            acc);
        acc = fmaf(s01, p[256],          acc);
        acc = fmaf(s10, p[DD * 256],     acc);
        acc = fmaf(s11, p[DD * 256 + 256], acc);
    }

    out[(size_t)row * 256 + h * 32 + lane] = acc;
}

// ---------------------------------------------------------------------------
extern "C" void kernel_launch(void* const* d_in, const int* in_sizes, int n_in,
                              void* d_out, int out_size)
{
    const float* query = (const float*)d_in[0];   // (2, LEN_Q, 256)
    const float* ref   = (const float*)d_in[1];   // (2, LEN_Q, 4, 2)
    const float* value = (const float*)d_in[2];   // (2, LEN_Q, 256)
    const float* Woff  = (const float*)d_in[3];   // (256, 256)
    const float* boff  = (const float*)d_in[4];   // (256,)
    const float* Wattn = (const float*)d_in[5];   // (256, 128)
    const float* battn = (const float*)d_in[6];   // (128,)
    float* out = (float*)d_out;                   // (2, LEN_Q, 256)

    dim3 ggrid((NQ + 127) / 128, 3);
    msda_gemm_kernel<<<ggrid, 256>>>(query, Woff, boff, Wattn, battn);

    const int nwarps  = NQ * 8;                   // one warp per (b,q,head)
    const int nblocks = (nwarps * 32 + 255) / 256;
    msda_sample_kernel<<<nblocks, 256>>>(ref, value, out);
}

// round 4
// speedup vs baseline: 1.2739x; 1.1289x over previous
#include <cuda_runtime.h>
#include <cuda_bf16.h>

#define LEN_Q   13294
#define NQ      (2 * LEN_Q)     // 26588 rows (b*LEN_Q + q)
#define N_OUT   384             // 256 offset cols + 128 attn cols
#define RB      16              // rows per sampler block

typedef unsigned long long ull;

// Scratch: projection output P[NQ][384]
__device__ float g_P[NQ * N_OUT];

// ---- packed f32x2 helpers (Blackwell) -------------------------------------
__device__ __forceinline__ void fma2(ull& d, ull a, ull b) {
    asm("fma.rn.f32x2 %0, %1, %2, %0;" : "+l"(d) : "l"(a), "l"(b));
}
__device__ __forceinline__ ull pack2(float lo, float hi) {
    ull r; asm("mov.b64 %0, {%1, %2};" : "=l"(r) : "f"(lo), "f"(hi)); return r;
}
__device__ __forceinline__ void unpack2(ull v, float& lo, float& hi) {
    asm("mov.b64 {%0, %1}, %2;" : "=f"(lo), "=f"(hi) : "l"(v));
}

// ---------------------------------------------------------------------------
// GEMM: P = Q @ [W_off | W_attn] + bias.  BM=128, BN=128, BK=16, 256 threads,
// 8x8 micro-tile per thread (f32x2 accumulators).  Measured at the fp32 FMA
// floor (~140us); unchanged this round.
// ---------------------------------------------------------------------------
__global__ __launch_bounds__(256) void msda_gemm_kernel(
    const float* __restrict__ Q,
    const float* __restrict__ Woff, const float* __restrict__ boff,
    const float* __restrict__ Wattn, const float* __restrict__ battn)
{
    __shared__ float As[16][136];   // [k][m], padded row
    __shared__ float Bs[16][128];   // [k][n]

    const int m0   = blockIdx.x * 128;
    const int nblk = blockIdx.y;

    const float* W; const float* bias; int ldW, n0;
    if (nblk < 2) { W = Woff;  bias = boff + nblk * 128; ldW = 256; n0 = nblk * 128; }
    else          { W = Wattn; bias = battn;             ldW = 128; n0 = 0;          }
    const int outn0 = nblk * 128;

    const int tid = threadIdx.x;
    const int tx  = tid & 15;       // col octet
    const int ty  = tid >> 4;       // row octet

    const int ar = tid >> 1;        // 0..127 (A tile row)
    const int ac = (tid & 1) * 8;   // 0/8    (A tile k)
    const int br = tid >> 4;        // 0..15  (B tile row)
    const int bc = (tid & 15) * 8;  // B tile col

    ull acc2[8][4];
#pragma unroll
    for (int i = 0; i < 8; i++)
#pragma unroll
        for (int jp = 0; jp < 4; jp++) acc2[i][jp] = 0ull;

#pragma unroll 1
    for (int k0 = 0; k0 < 256; k0 += 16) {
        float4 a0 = make_float4(0.f,0.f,0.f,0.f), a1 = a0;
        if (m0 + ar < NQ) {
            const float* qp = &Q[(size_t)(m0 + ar) * 256 + k0 + ac];
            a0 = *(const float4*)qp;
            a1 = *(const float4*)(qp + 4);
        }
        const float* wp = &W[(size_t)(k0 + br) * ldW + n0 + bc];
        float4 b0 = *(const float4*)wp;
        float4 b1 = *(const float4*)(wp + 4);

        __syncthreads();
        As[ac + 0][ar] = a0.x; As[ac + 1][ar] = a0.y;
        As[ac + 2][ar] = a0.z; As[ac + 3][ar] = a0.w;
        As[ac + 4][ar] = a1.x; As[ac + 5][ar] = a1.y;
        As[ac + 6][ar] = a1.z; As[ac + 7][ar] = a1.w;
        *(float4*)&Bs[br][bc]     = b0;
        *(float4*)&Bs[br][bc + 4] = b1;
        __syncthreads();

#pragma unroll
        for (int k = 0; k < 16; k++) {
            float4 av0 = *(const float4*)&As[k][ty * 8];
            float4 av1 = *(const float4*)&As[k][ty * 8 + 4];
            longlong2 bv0 = *(const longlong2*)&Bs[k][tx * 8];
            longlong2 bv1 = *(const longlong2*)&Bs[k][tx * 8 + 4];
            ull bb[4] = { (ull)bv0.x, (ull)bv0.y, (ull)bv1.x, (ull)bv1.y };
            float aa[8] = { av0.x, av0.y, av0.z, av0.w,
                            av1.x, av1.y, av1.z, av1.w };
#pragma unroll
            for (int i = 0; i < 8; i++) {
                ull ad = pack2(aa[i], aa[i]);
#pragma unroll
                for (int jp = 0; jp < 4; jp++) fma2(acc2[i][jp], ad, bb[jp]);
            }
        }
    }

    const float4 bq0 = *(const float4*)&bias[tx * 8];
    const float4 bq1 = *(const float4*)&bias[tx * 8 + 4];
    const float bcol[8] = { bq0.x, bq0.y, bq0.z, bq0.w,
                            bq1.x, bq1.y, bq1.z, bq1.w };

#pragma unroll
    for (int i = 0; i < 8; i++) {
        const int m = m0 + ty * 8 + i;
        if (m < NQ) {
            float o[8];
#pragma unroll
            for (int jp = 0; jp < 4; jp++) unpack2(acc2[i][jp], o[jp*2], o[jp*2+1]);
            float4 s0 = make_float4(o[0]+bcol[0], o[1]+bcol[1], o[2]+bcol[2], o[3]+bcol[3]);
            float4 s1 = make_float4(o[4]+bcol[4], o[5]+bcol[5], o[6]+bcol[6], o[7]+bcol[7]);
            float* gp = &g_P[(size_t)m * N_OUT + outn0 + tx * 8];
            *(float4*)gp       = s0;
            *(float4*)(gp + 4) = s1;
        }
    }
}

// ---------------------------------------------------------------------------
// Sampling v3: block = 16 rows, two phases through shared memory.
// Phase 1: 2 threads per (row,head) compute softmax + per-point
//          (4 corner weights, clamped flat index) into smem.
// Phase 2: each lane owns 4 consecutive channels (float4); per point:
//          1 broadcast LDS.128 + 1 LDS.32 + 4 coalesced LDG.128 + 16 FFMA.
//          No shuffles anywhere in the hot loop.
// ---------------------------------------------------------------------------
__global__ __launch_bounds__(256) void msda_sample_kernel(
    const float* __restrict__ ref,    // (2, LEN_Q, 4, 2)
    const float* __restrict__ value,  // (2, LEN_Q, 256)
    float* __restrict__ out)          // (2, LEN_Q, 256)
{
    __shared__ float4 s_w[RB][8][17];   // padded: head stride 17 -> no bank conflict
    __shared__ int    s_i[RB][8][17];

    const int row0 = blockIdx.x * RB;
    const int t    = threadIdx.x;

    // ---------------- Phase 1 ----------------
    {
        const int g    = t >> 1;        // 0..127: (row_local, head)
        const int half = t & 1;         // which 8 points
        const int rl   = g >> 3;
        const int h    = g & 7;
        const int row  = row0 + rl;

        if (row < NQ) {
            const float* Prow = g_P + (size_t)row * N_OUT;

            // softmax denominator over all 16 logits (both halves recompute)
            float lg[16];
#pragma unroll
            for (int v = 0; v < 4; v++) {
                float4 q = *(const float4*)&Prow[256 + h * 16 + v * 4];
                lg[v*4+0] = q.x; lg[v*4+1] = q.y; lg[v*4+2] = q.z; lg[v*4+3] = q.w;
            }
            float mx = lg[0];
#pragma unroll
            for (int v = 1; v < 16; v++) mx = fmaxf(mx, lg[v]);
            float ssum = 0.f;
#pragma unroll
            for (int v = 0; v < 16; v++) ssum += __expf(lg[v] - mx);
            const float inv = 1.f / ssum;

#pragma unroll
            for (int jj = 0; jj < 8; jj++) {
                const int j = half * 8 + jj;
                const int l = j >> 2;
                const int D = (l == 0) ? 100 : (l == 1) ? 50 : (l == 2) ? 25 : 13;

                const float wgt  = __expf(lg[j] - mx) * inv;
                const float offx = Prow[h * 32 + j * 2];
                const float offy = Prow[h * 32 + j * 2 + 1];
                const float rx = ref[(size_t)(row * 4 + l) * 2 + 0];
                const float ry = ref[(size_t)(row * 4 + l) * 2 + 1];
                const float x = fmaf(rx, (float)D, offx) - 0.5f;
                const float y = fmaf(ry, (float)D, offy) - 0.5f;

                const float xf = floorf(x), yf = floorf(y);
                const int x0 = (int)xf, y0 = (int)yf;
                const float fx = x - xf, fy = y - yf;

                const float gx0 = (x0 >= 0     && x0 < D)     ? (1.f - fx) : 0.f;
                const float gx1 = (x0 + 1 >= 0 && x0 + 1 < D) ? fx         : 0.f;
                const float gy0 = (y0 >= 0     && y0 < D)     ? (1.f - fy) : 0.f;
                const float gy1 = (y0 + 1 >= 0 && y0 + 1 < D) ? fy         : 0.f;

                const int cx = min(max(x0, 0), D - 2);
                const int cy = min(max(y0, 0), D - 2);
                const float wl = (x0 < 0) ? gx1 : ((x0 <= D - 2) ? gx0 : 0.f);
                const float wr = (x0 < 0) ? 0.f : ((x0 <= D - 2) ? gx1 : gx0);
                const float wt = (y0 < 0) ? gy1 : ((y0 <= D - 2) ? gy0 : 0.f);
                const float wb = (y0 < 0) ? 0.f : ((y0 <= D - 2) ? gy1 : gy0);

                s_w[rl][h][j] = make_float4(wgt * wl * wt, wgt * wr * wt,
                                            wgt * wl * wb, wgt * wr * wb);
                s_i[rl][h][j] = cy * D + cx;
            }
        }
    }
    __syncthreads();

    // ---------------- Phase 2 ----------------
#pragma unroll
    for (int it = 0; it < 4; it++) {
        const int T   = it * 256 + t;        // warp covers half a row, coalesced
        const int rl  = T >> 6;
        const int c4  = T & 63;              // float4 slot: head = c4>>3
        const int row = row0 + rl;
        if (row >= NQ) continue;

        const int h = c4 >> 3;
        const int b = (row >= LEN_Q) ? 1 : 0;
        const float* vb = value + (size_t)b * LEN_Q * 256 + h * 32 + (c4 & 7) * 4;

        float4 acc = make_float4(0.f, 0.f, 0.f, 0.f);
#pragma unroll
        for (int j = 0; j < 16; j++) {
            const int l    = j >> 2;                          // compile-time
            const int DD   = (l == 0) ? 100 : (l == 1) ? 50 : (l == 2) ? 25 : 13;
            const int BASE = (l == 0) ? 0 : (l == 1) ? 10000 : (l == 2) ? 12500 : 13125;

            const float4 w  = s_w[rl][h][j];
            const int    ix = s_i[rl][h][j];
            const float* p  = vb + (size_t)(BASE + ix) * 256;

            const float4 v00 = *(const float4*)p;
            const float4 v01 = *(const float4*)(p + 256);
            const float4 v10 = *(const float4*)(p + DD * 256);
            const float4 v11 = *(const float4*)(p + DD * 256 + 256);

            acc.x = fmaf(w.x, v00.x, acc.x);
            acc.y = fmaf(w.x, v00.y, acc.y);
            acc.z = fmaf(w.x, v00.z, acc.z);
            acc.w = fmaf(w.x, v00.w, acc.w);
            acc.x = fmaf(w.y, v01.x, acc.x);
            acc.y = fmaf(w.y, v01.y, acc.y);
            acc.z = fmaf(w.y, v01.z, acc.z);
            acc.w = fmaf(w.y, v01.w, acc.w);
            acc.x = fmaf(w.z, v10.x, acc.x);
            acc.y = fmaf(w.z, v10.y, acc.y);
            acc.z = fmaf(w.z, v10.z, acc.z);
            acc.w = fmaf(w.z, v10.w, acc.w);
            acc.x = fmaf(w.w, v11.x, acc.x);
            acc.y = fmaf(w.w, v11.y, acc.y);
            acc.z = fmaf(w.w, v11.z, acc.z);
            acc.w = fmaf(w.w, v11.w, acc.w);
        }

        *(float4*)&out[(size_t)row * 256 + c4 * 4] = acc;
    }
}

// ---------------------------------------------------------------------------
extern "C" void kernel_launch(void* const* d_in, const int* in_sizes, int n_in,
                              void* d_out, int out_size)
{
    const float* query = (const float*)d_in[0];   // (2, LEN_Q, 256)
    const float* ref   = (const float*)d_in[1];   // (2, LEN_Q, 4, 2)
    const float* value = (const float*)d_in[2];   // (2, LEN_Q, 256)
    const float* Woff  = (const float*)d_in[3];   // (256, 256)
    const float* boff  = (const float*)d_in[4];   // (256,)
    const float* Wattn = (const float*)d_in[5];   // (256, 128)
    const float* battn = (const float*)d_in[6];   // (128,)
    float* out = (float*)d_out;                   // (2, LEN_Q, 256)

    dim3 ggrid((NQ + 127) / 128, 3);
    msda_gemm_kernel<<<ggrid, 256>>>(query, Woff, boff, Wattn, battn);

    const int nblocks = (NQ + RB - 1) / RB;       // 1662
    msda_sample_kernel<<<nblocks, 256>>>(ref, value, out);
}

// round 5
// speedup vs baseline: 1.5805x; 1.2407x over previous
#include <cuda_runtime.h>
#include <cuda_bf16.h>

#define LEN_Q   13294
#define NQ      (2 * LEN_Q)     // 26588 rows (b*LEN_Q + q)
#define N_OUT   384             // 256 offset cols + 128 attn cols
#define RB      16              // rows per sampler block

// Scratch: projection output P[NQ][384]
__device__ float g_P[NQ * N_OUT];

// ---------------------------------------------------------------------------
// tf32 helpers
// ---------------------------------------------------------------------------
__device__ __forceinline__ unsigned f2tf32(float f) {
    unsigned u;
    asm("cvt.rna.tf32.f32 %0, %1;" : "=r"(u) : "f"(f));
    return u;
}
__device__ __forceinline__ void mma_tf32(float* d, const unsigned* a, const unsigned* b) {
    asm volatile(
        "mma.sync.aligned.m16n8k8.row.col.f32.tf32.tf32.f32 "
        "{%0,%1,%2,%3}, {%4,%5,%6,%7}, {%8,%9}, {%0,%1,%2,%3};"
        : "+f"(d[0]), "+f"(d[1]), "+f"(d[2]), "+f"(d[3])
        : "r"(a[0]), "r"(a[1]), "r"(a[2]), "r"(a[3]),
          "r"(b[0]), "r"(b[1]));
}

// ---------------------------------------------------------------------------
// GEMM v3 (tensor cores): P = Q @ [W_off | W_attn] + bias, tf32 mma.sync.
// BM=128, BN=128, BK=32, 256 threads = 8 warps, warp tile 64x32 (4x4 m16n8k8).
// grid = (ceil(NQ/128), 3): y 0,1 -> W_off halves; 2 -> W_attn.
// ---------------------------------------------------------------------------
__global__ __launch_bounds__(256) void msda_gemm_kernel(
    const float* __restrict__ Q,
    const float* __restrict__ Woff, const float* __restrict__ boff,
    const float* __restrict__ Wattn, const float* __restrict__ battn)
{
    __shared__ unsigned As[128][36];   // [m][k], pad 32->36 (conflict-free frags)
    __shared__ unsigned Bs[32][132];   // [k][n], pad 128->132

    const int m0   = blockIdx.x * 128;
    const int nblk = blockIdx.y;

    const float* W; const float* bias; int ldW, n0;
    if (nblk < 2) { W = Woff;  bias = boff + nblk * 128; ldW = 256; n0 = nblk * 128; }
    else          { W = Wattn; bias = battn;             ldW = 128; n0 = 0;          }
    const int outn0 = nblk * 128;

    const int tid  = threadIdx.x;
    const int wid  = tid >> 5;
    const int lane = tid & 31;
    const int g    = lane >> 2;        // groupID 0..7
    const int tig  = lane & 3;         // thread-in-group 0..3
    const int wm   = wid & 1;          // warp M index (0..1) -> rows wm*64
    const int wn   = wid >> 1;         // warp N index (0..3) -> cols wn*32

    // global load mapping
    const int arow = tid >> 1;         // 0..127
    const int acol = (tid & 1) * 16;   // 0/16
    const int brow = tid >> 3;         // 0..31
    const int bcol = (tid & 7) * 16;   // 0..112

    float acc[4][4][4];
#pragma unroll
    for (int tm = 0; tm < 4; tm++)
#pragma unroll
        for (int tn = 0; tn < 4; tn++)
#pragma unroll
            for (int r = 0; r < 4; r++) acc[tm][tn][r] = 0.f;

#pragma unroll 1
    for (int k0 = 0; k0 < 256; k0 += 32) {
        // stage global -> regs
        float4 aq[4];
        if (m0 + arow < NQ) {
            const float* qp = &Q[(size_t)(m0 + arow) * 256 + k0 + acol];
#pragma unroll
            for (int i = 0; i < 4; i++) aq[i] = *(const float4*)(qp + i * 4);
        } else {
#pragma unroll
            for (int i = 0; i < 4; i++) aq[i] = make_float4(0.f, 0.f, 0.f, 0.f);
        }
        float4 bw[4];
        const float* wp = &W[(size_t)(k0 + brow) * ldW + n0 + bcol];
#pragma unroll
        for (int i = 0; i < 4; i++) bw[i] = *(const float4*)(wp + i * 4);

        __syncthreads();
#pragma unroll
        for (int i = 0; i < 4; i++) {
            uint4 ua = make_uint4(f2tf32(aq[i].x), f2tf32(aq[i].y),
                                  f2tf32(aq[i].z), f2tf32(aq[i].w));
            *(uint4*)&As[arow][acol + i * 4] = ua;
            uint4 ub = make_uint4(f2tf32(bw[i].x), f2tf32(bw[i].y),
                                  f2tf32(bw[i].z), f2tf32(bw[i].w));
            *(uint4*)&Bs[brow][bcol + i * 4] = ub;
        }
        __syncthreads();

#pragma unroll
        for (int ks = 0; ks < 4; ks++) {
            const int kk = ks * 8;
            unsigned af[4][4];
#pragma unroll
            for (int tm = 0; tm < 4; tm++) {
                const int r = wm * 64 + tm * 16;
                af[tm][0] = As[r + g][kk + tig];
                af[tm][1] = As[r + g + 8][kk + tig];
                af[tm][2] = As[r + g][kk + tig + 4];
                af[tm][3] = As[r + g + 8][kk + tig + 4];
            }
            unsigned bf[4][2];
#pragma unroll
            for (int tn = 0; tn < 4; tn++) {
                const int c = wn * 32 + tn * 8;
                bf[tn][0] = Bs[kk + tig][c + g];
                bf[tn][1] = Bs[kk + tig + 4][c + g];
            }
#pragma unroll
            for (int tm = 0; tm < 4; tm++)
#pragma unroll
                for (int tn = 0; tn < 4; tn++)
                    mma_tf32(acc[tm][tn], af[tm], bf[tn]);
        }
    }

    // epilogue: bias + store (d-layout: rows g/g+8, cols tig*2, tig*2+1)
#pragma unroll
    for (int tn = 0; tn < 4; tn++) {
        const int cl = wn * 32 + tn * 8 + tig * 2;        // local col
        const float2 bv = *(const float2*)&bias[cl];
#pragma unroll
        for (int tm = 0; tm < 4; tm++) {
            const int r0 = m0 + wm * 64 + tm * 16 + g;
            const int r1 = r0 + 8;
            if (r0 < NQ) {
                float2 o = make_float2(acc[tm][tn][0] + bv.x, acc[tm][tn][1] + bv.y);
                *(float2*)&g_P[(size_t)r0 * N_OUT + outn0 + cl] = o;
            }
            if (r1 < NQ) {
                float2 o = make_float2(acc[tm][tn][2] + bv.x, acc[tm][tn][3] + bv.y);
                *(float2*)&g_P[(size_t)r1 * N_OUT + outn0 + cl] = o;
            }
        }
    }
}

// ---------------------------------------------------------------------------
// Sampling v3.1: block = 16 rows, two phases through shared memory.
// launch_bounds(256,5) to raise occupancy (R4: reg-limited at 46% occ).
// ---------------------------------------------------------------------------
__global__ __launch_bounds__(256, 5) void msda_sample_kernel(
    const float* __restrict__ ref,    // (2, LEN_Q, 4, 2)
    const float* __restrict__ value,  // (2, LEN_Q, 256)
    float* __restrict__ out)          // (2, LEN_Q, 256)
{
    __shared__ float4 s_w[RB][8][17];   // padded: head stride 17
    __shared__ int    s_i[RB][8][17];

    const int row0 = blockIdx.x * RB;
    const int t    = threadIdx.x;

    // ---------------- Phase 1 ----------------
    {
        const int gq   = t >> 1;        // 0..127: (row_local, head)
        const int half = t & 1;         // which 8 points
        const int rl   = gq >> 3;
        const int h    = gq & 7;
        const int row  = row0 + rl;

        if (row < NQ) {
            const float* Prow = g_P + (size_t)row * N_OUT;

            float lg[16];
#pragma unroll
            for (int v = 0; v < 4; v++) {
                float4 q = *(const float4*)&Prow[256 + h * 16 + v * 4];
                lg[v*4+0] = q.x; lg[v*4+1] = q.y; lg[v*4+2] = q.z; lg[v*4+3] = q.w;
            }
            float mx = lg[0];
#pragma unroll
            for (int v = 1; v < 16; v++) mx = fmaxf(mx, lg[v]);
            float ssum = 0.f;
#pragma unroll
            for (int v = 0; v < 16; v++) ssum += __expf(lg[v] - mx);
            const float inv = 1.f / ssum;

#pragma unroll
            for (int jj = 0; jj < 8; jj++) {
                const int j = half * 8 + jj;
                const int l = j >> 2;
                const int D = (l == 0) ? 100 : (l == 1) ? 50 : (l == 2) ? 25 : 13;

                const float wgt  = __expf(lg[j] - mx) * inv;
                const float offx = Prow[h * 32 + j * 2];
                const float offy = Prow[h * 32 + j * 2 + 1];
                const float rx = ref[(size_t)(row * 4 + l) * 2 + 0];
                const float ry = ref[(size_t)(row * 4 + l) * 2 + 1];
                const float x = fmaf(rx, (float)D, offx) - 0.5f;
                const float y = fmaf(ry, (float)D, offy) - 0.5f;

                const float xf = floorf(x), yf = floorf(y);
                const int x0 = (int)xf, y0 = (int)yf;
                const float fx = x - xf, fy = y - yf;

                const float gx0 = (x0 >= 0     && x0 < D)     ? (1.f - fx) : 0.f;
                const float gx1 = (x0 + 1 >= 0 && x0 + 1 < D) ? fx         : 0.f;
                const float gy0 = (y0 >= 0     && y0 < D)     ? (1.f - fy) : 0.f;
                const float gy1 = (y0 + 1 >= 0 && y0 + 1 < D) ? fy         : 0.f;

                const int cx = min(max(x0, 0), D - 2);
                const int cy = min(max(y0, 0), D - 2);
                const float wl = (x0 < 0) ? gx1 : ((x0 <= D - 2) ? gx0 : 0.f);
                const float wr = (x0 < 0) ? 0.f : ((x0 <= D - 2) ? gx1 : gx0);
                const float wt = (y0 < 0) ? gy1 : ((y0 <= D - 2) ? gy0 : 0.f);
                const float wb = (y0 < 0) ? 0.f : ((y0 <= D - 2) ? gy1 : gy0);

                s_w[rl][h][j] = make_float4(wgt * wl * wt, wgt * wr * wt,
                                            wgt * wl * wb, wgt * wr * wb);
                s_i[rl][h][j] = cy * D + cx;
            }
        }
    }
    __syncthreads();

    // ---------------- Phase 2 ----------------
#pragma unroll
    for (int it = 0; it < 4; it++) {
        const int T   = it * 256 + t;
        const int rl  = T >> 6;
        const int c4  = T & 63;              // float4 slot: head = c4>>3
        const int row = row0 + rl;
        if (row >= NQ) continue;

        const int h = c4 >> 3;
        const int b = (row >= LEN_Q) ? 1 : 0;
        const float* vb = value + (size_t)b * LEN_Q * 256 + h * 32 + (c4 & 7) * 4;

        float4 acc = make_float4(0.f, 0.f, 0.f, 0.f);
#pragma unroll
        for (int j = 0; j < 16; j++) {
            const int l    = j >> 2;                          // compile-time
            const int DD   = (l == 0) ? 100 : (l == 1) ? 50 : (l == 2) ? 25 : 13;
            const int BASE = (l == 0) ? 0 : (l == 1) ? 10000 : (l == 2) ? 12500 : 13125;

            const float4 w  = s_w[rl][h][j];
            const int    ix = s_i[rl][h][j];
            const float* p  = vb + (size_t)(BASE + ix) * 256;

            const float4 v00 = *(const float4*)p;
            const float4 v01 = *(const float4*)(p + 256);
            const float4 v10 = *(const float4*)(p + DD * 256);
            const float4 v11 = *(const float4*)(p + DD * 256 + 256);

            acc.x = fmaf(w.x, v00.x, acc.x);
            acc.y = fmaf(w.x, v00.y, acc.y);
            acc.z = fmaf(w.x, v00.z, acc.z);
            acc.w = fmaf(w.x, v00.w, acc.w);
            acc.x = fmaf(w.y, v01.x, acc.x);
            acc.y = fmaf(w.y, v01.y, acc.y);
            acc.z = fmaf(w.y, v01.z, acc.z);
            acc.w = fmaf(w.y, v01.w, acc.w);
            acc.x = fmaf(w.z, v10.x, acc.x);
            acc.y = fmaf(w.z, v10.y, acc.y);
            acc.z = fmaf(w.z, v10.z, acc.z);
            acc.w = fmaf(w.z, v10.w, acc.w);
            acc.x = fmaf(w.w, v11.x, acc.x);
            acc.y = fmaf(w.w, v11.y, acc.y);
            acc.z = fmaf(w.w, v11.z, acc.z);
            acc.w = fmaf(w.w, v11.w, acc.w);
        }

        *(float4*)&out[(size_t)row * 256 + c4 * 4] = acc;
    }
}

// ---------------------------------------------------------------------------
extern "C" void kernel_launch(void* const* d_in, const int* in_sizes, int n_in,
                              void* d_out, int out_size)
{
    const float* query = (const float*)d_in[0];   // (2, LEN_Q, 256)
    const float* ref   = (const float*)d_in[1];   // (2, LEN_Q, 4, 2)
    const float* value = (const float*)d_in[2];   // (2, LEN_Q, 256)
    const float* Woff  = (const float*)d_in[3];   // (256, 256)
    const float* boff  = (const float*)d_in[4];   // (256,)
    const float* Wattn = (const float*)d_in[5];   // (256, 128)
    const float* battn = (const float*)d_in[6];   // (128,)
    float* out = (float*)d_out;                   // (2, LEN_Q, 256)

    dim3 ggrid((NQ + 127) / 128, 3);
    msda_gemm_kernel<<<ggrid, 256>>>(query, Woff, boff, Wattn, battn);

    const int nblocks = (NQ + RB - 1) / RB;       // 1662
    msda_sample_kernel<<<nblocks, 256>>>(ref, value, out);
}

// round 6
// speedup vs baseline: 1.9276x; 1.2196x over previous
#include <cuda_runtime.h>
#include <cuda_bf16.h>

#define LEN_Q   13294
#define NQ      (2 * LEN_Q)     // 26588 rows (b*LEN_Q + q)
#define N_OUT   384             // 256 offset cols + 128 attn cols
#define RB      16              // rows per sampler block

// Scratch: projection output P[NQ][384]
__device__ float g_P[NQ * N_OUT];

// ---------------------------------------------------------------------------
// tf32 / cp.async helpers
// ---------------------------------------------------------------------------
__device__ __forceinline__ unsigned f2tf32(float f) {
    unsigned u;
    asm("cvt.rna.tf32.f32 %0, %1;" : "=r"(u) : "f"(f));
    return u;
}
__device__ __forceinline__ void mma_tf32(float* d, const unsigned* a, const unsigned* b) {
    asm volatile(
        "mma.sync.aligned.m16n8k8.row.col.f32.tf32.tf32.f32 "
        "{%0,%1,%2,%3}, {%4,%5,%6,%7}, {%8,%9}, {%0,%1,%2,%3};"
        : "+f"(d[0]), "+f"(d[1]), "+f"(d[2]), "+f"(d[3])
        : "r"(a[0]), "r"(a[1]), "r"(a[2]), "r"(a[3]),
          "r"(b[0]), "r"(b[1]));
}
__device__ __forceinline__ unsigned smem_u32(const void* p) {
    return (unsigned)__cvta_generic_to_shared(p);
}
__device__ __forceinline__ void cp_async16(unsigned dst, const void* src, int src_bytes) {
    asm volatile("cp.async.ca.shared.global [%0], [%1], 16, %2;"
                 :: "r"(dst), "l"(src), "r"(src_bytes));
}
__device__ __forceinline__ void cp_commit() {
    asm volatile("cp.async.commit_group;");
}
template <int N>
__device__ __forceinline__ void cp_wait() {
    asm volatile("cp.async.wait_group %0;" :: "n"(N));
}

// ---------------------------------------------------------------------------
// GEMM v4: tf32 mma.sync + cp.async double buffering.
// BM=128, BN=128, BK=16, 2 stages, 256 threads = 8 warps, warp tile 64x32.
// fp32 staged raw in smem; cvt to tf32 at fragment-load time.
// grid = (ceil(NQ/128), 3): y 0,1 -> W_off halves; 2 -> W_attn.
// ---------------------------------------------------------------------------
#define LDA 20     // 16 + 4 pad (floats)  -> conflict-free A fragments
#define LDB 132    // 128 + 4 pad (floats)

__global__ __launch_bounds__(256) void msda_gemm_kernel(
    const float* __restrict__ Q,
    const float* __restrict__ Woff, const float* __restrict__ boff,
    const float* __restrict__ Wattn, const float* __restrict__ battn)
{
    __shared__ float As[2][128 * LDA];   // [m][k]
    __shared__ float Bs[2][16 * LDB];    // [k][n]

    const int m0   = blockIdx.x * 128;
    const int nblk = blockIdx.y;

    const float* W; const float* bias; int ldW, n0;
    if (nblk < 2) { W = Woff;  bias = boff + nblk * 128; ldW = 256; n0 = nblk * 128; }
    else          { W = Wattn; bias = battn;             ldW = 128; n0 = 0;          }
    const int outn0 = nblk * 128;

    const int tid  = threadIdx.x;
    const int wid  = tid >> 5;
    const int lane = tid & 31;
    const int g    = lane >> 2;        // groupID 0..7
    const int tig  = lane & 3;         // thread-in-group 0..3
    const int wm   = wid & 1;          // rows wm*64
    const int wn   = wid >> 1;         // cols wn*32

    // cp.async chunk mapping: A tile 128x16 floats = 512 16B-chunks, 2/thread
    //   chunk c: row = c>>2, kc = (c&3)*4
    // B tile 16x128 floats = 512 chunks, 2/thread
    //   chunk c: row = c>>5, cc = (c&31)*4
    const int ac0r = tid >> 2,        ac0k = (tid & 3) * 4;
    const int ac1r = (tid + 256) >> 2, ac1k = ((tid + 256) & 3) * 4;
    const int bc0r = tid >> 5,        bc0c = (tid & 31) * 4;
    const int bc1r = (tid + 256) >> 5, bc1c = ((tid + 256) & 31) * 4;

    const unsigned sA[2] = { smem_u32(&As[0][0]), smem_u32(&As[1][0]) };
    const unsigned sB[2] = { smem_u32(&Bs[0][0]), smem_u32(&Bs[1][0]) };

    auto load_tile = [&](int s, int k0) {
        int v0 = (m0 + ac0r < NQ) ? 16 : 0;
        int v1 = (m0 + ac1r < NQ) ? 16 : 0;
        cp_async16(sA[s] + (ac0r * LDA + ac0k) * 4,
                   &Q[(size_t)(m0 + ac0r) * 256 + k0 + ac0k], v0);
        cp_async16(sA[s] + (ac1r * LDA + ac1k) * 4,
                   &Q[(size_t)(m0 + ac1r) * 256 + k0 + ac1k], v1);
        cp_async16(sB[s] + (bc0r * LDB + bc0c) * 4,
                   &W[(size_t)(k0 + bc0r) * ldW + n0 + bc0c], 16);
        cp_async16(sB[s] + (bc1r * LDB + bc1c) * 4,
                   &W[(size_t)(k0 + bc1r) * ldW + n0 + bc1c], 16);
        cp_commit();
    };

    float acc[4][4][4];
#pragma unroll
    for (int tm = 0; tm < 4; tm++)
#pragma unroll
        for (int tn = 0; tn < 4; tn++)
#pragma unroll
            for (int r = 0; r < 4; r++) acc[tm][tn][r] = 0.f;

    load_tile(0, 0);

#pragma unroll 1
    for (int it = 0; it < 16; it++) {
        const int s = it & 1;
        if (it + 1 < 16) {
            load_tile(1 - s, (it + 1) * 16);
            cp_wait<1>();
        } else {
            cp_wait<0>();
        }
        __syncthreads();

        const float* Ab = &As[s][0];
        const float* Bb = &Bs[s][0];
#pragma unroll
        for (int ks = 0; ks < 2; ks++) {
            const int kk = ks * 8;
            unsigned af[4][4];
#pragma unroll
            for (int tm = 0; tm < 4; tm++) {
                const int r = wm * 64 + tm * 16;
                af[tm][0] = f2tf32(Ab[(r + g)     * LDA + kk + tig]);
                af[tm][1] = f2tf32(Ab[(r + g + 8) * LDA + kk + tig]);
                af[tm][2] = f2tf32(Ab[(r + g)     * LDA + kk + tig + 4]);
                af[tm][3] = f2tf32(Ab[(r + g + 8) * LDA + kk + tig + 4]);
            }
            unsigned bf[4][2];
#pragma unroll
            for (int tn = 0; tn < 4; tn++) {
                const int c = wn * 32 + tn * 8;
                bf[tn][0] = f2tf32(Bb[(kk + tig)     * LDB + c + g]);
                bf[tn][1] = f2tf32(Bb[(kk + tig + 4) * LDB + c + g]);
            }
#pragma unroll
            for (int tm = 0; tm < 4; tm++)
#pragma unroll
                for (int tn = 0; tn < 4; tn++)
                    mma_tf32(acc[tm][tn], af[tm], bf[tn]);
        }
        __syncthreads();
    }

    // epilogue: bias + store (d-layout: rows g/g+8, cols tig*2, tig*2+1)
#pragma unroll
    for (int tn = 0; tn < 4; tn++) {
        const int cl = wn * 32 + tn * 8 + tig * 2;
        const float2 bv = *(const float2*)&bias[cl];
#pragma unroll
        for (int tm = 0; tm < 4; tm++) {
            const int r0 = m0 + wm * 64 + tm * 16 + g;
            const int r1 = r0 + 8;
            if (r0 < NQ) {
                float2 o = make_float2(acc[tm][tn][0] + bv.x, acc[tm][tn][1] + bv.y);
                *(float2*)&g_P[(size_t)r0 * N_OUT + outn0 + cl] = o;
            }
            if (r1 < NQ) {
                float2 o = make_float2(acc[tm][tn][2] + bv.x, acc[tm][tn][3] + bv.y);
                *(float2*)&g_P[(size_t)r1 * N_OUT + outn0 + cl] = o;
            }
        }
    }
}

// ---------------------------------------------------------------------------
// Sampling v3 (R4 verbatim — no launch_bounds cap; regs>occupancy tradeoff
// measured: 54 regs / 46% occ = 111us beats 48 regs / 56% occ = 131us).
// ---------------------------------------------------------------------------
__global__ __launch_bounds__(256) void msda_sample_kernel(
    const float* __restrict__ ref,    // (2, LEN_Q, 4, 2)
    const float* __restrict__ value,  // (2, LEN_Q, 256)
    float* __restrict__ out)          // (2, LEN_Q, 256)
{
    __shared__ float4 s_w[RB][8][17];   // padded: head stride 17
    __shared__ int    s_i[RB][8][17];

    const int row0 = blockIdx.x * RB;
    const int t    = threadIdx.x;

    // ---------------- Phase 1 ----------------
    {
        const int gq   = t >> 1;        // 0..127: (row_local, head)
        const int half = t & 1;         // which 8 points
        const int rl   = gq >> 3;
        const int h    = gq & 7;
        const int row  = row0 + rl;

        if (row < NQ) {
            const float* Prow = g_P + (size_t)row * N_OUT;

            float lg[16];
#pragma unroll
            for (int v = 0; v < 4; v++) {
                float4 q = *(const float4*)&Prow[256 + h * 16 + v * 4];
                lg[v*4+0] = q.x; lg[v*4+1] = q.y; lg[v*4+2] = q.z; lg[v*4+3] = q.w;
            }
            float mx = lg[0];
#pragma unroll
            for (int v = 1; v < 16; v++) mx = fmaxf(mx, lg[v]);
            float ssum = 0.f;
#pragma unroll
            for (int v = 0; v < 16; v++) ssum += __expf(lg[v] - mx);
            const float inv = 1.f / ssum;

#pragma unroll
            for (int jj = 0; jj < 8; jj++) {
                const int j = half * 8 + jj;
                const int l = j >> 2;
                const int D = (l == 0) ? 100 : (l == 1) ? 50 : (l == 2) ? 25 : 13;

                const float wgt  = __expf(lg[j] - mx) * inv;
                const float offx = Prow[h * 32 + j * 2];
                const float offy = Prow[h * 32 + j * 2 + 1];
                const float rx = ref[(size_t)(row * 4 + l) * 2 + 0];
                const float ry = ref[(size_t)(row * 4 + l) * 2 + 1];
                const float x = fmaf(rx, (float)D, offx) - 0.5f;
                const float y = fmaf(ry, (float)D, offy) - 0.5f;

                const float xf = floorf(x), yf = floorf(y);
                const int x0 = (int)xf, y0 = (int)yf;
                const float fx = x - xf, fy = y - yf;

                const float gx0 = (x0 >= 0     && x0 < D)     ? (1.f - fx) : 0.f;
                const float gx1 = (x0 + 1 >= 0 && x0 + 1 < D) ? fx         : 0.f;
                const float gy0 = (y0 >= 0     && y0 < D)     ? (1.f - fy) : 0.f;
                const float gy1 = (y0 + 1 >= 0 && y0 + 1 < D) ? fy         : 0.f;

                const int cx = min(max(x0, 0), D - 2);
                const int cy = min(max(y0, 0), D - 2);
                const float wl = (x0 < 0) ? gx1 : ((x0 <= D - 2) ? gx0 : 0.f);
                const float wr = (x0 < 0) ? 0.f : ((x0 <= D - 2) ? gx1 : gx0);
                const float wt = (y0 < 0) ? gy1 : ((y0 <= D - 2) ? gy0 : 0.f);
                const float wb = (y0 < 0) ? 0.f : ((y0 <= D - 2) ? gy1 : gy0);

                s_w[rl][h][j] = make_float4(wgt * wl * wt, wgt * wr * wt,
                                            wgt * wl * wb, wgt * wr * wb);
                s_i[rl][h][j] = cy * D + cx;
            }
        }
    }
    __syncthreads();

    // ---------------- Phase 2 ----------------
#pragma unroll
    for (int it = 0; it < 4; it++) {
        const int T   = it * 256 + t;
        const int rl  = T >> 6;
        const int c4  = T & 63;              // float4 slot: head = c4>>3
        const int row = row0 + rl;
        if (row >= NQ) continue;

        const int h = c4 >> 3;
        const int b = (row >= LEN_Q) ? 1 : 0;
        const float* vb = value + (size_t)b * LEN_Q * 256 + h * 32 + (c4 & 7) * 4;

        float4 acc = make_float4(0.f, 0.f, 0.f, 0.f);
#pragma unroll
        for (int j = 0; j < 16; j++) {
            const int l    = j >> 2;                          // compile-time
            const int DD   = (l == 0) ? 100 : (l == 1) ? 50 : (l == 2) ? 25 : 13;
            const int BASE = (l == 0) ? 0 : (l == 1) ? 10000 : (l == 2) ? 12500 : 13125;

            const float4 w  = s_w[rl][h][j];
            const int    ix = s_i[rl][h][j];
            const float* p  = vb + (size_t)(BASE + ix) * 256;

            const float4 v00 = *(const float4*)p;
            const float4 v01 = *(const float4*)(p + 256);
            const float4 v10 = *(const float4*)(p + DD * 256);
            const float4 v11 = *(const float4*)(p + DD * 256 + 256);

            acc.x = fmaf(w.x, v00.x, acc.x);
            acc.y = fmaf(w.x, v00.y, acc.y);
            acc.z = fmaf(w.x, v00.z, acc.z);
            acc.w = fmaf(w.x, v00.w, acc.w);
            acc.x = fmaf(w.y, v01.x, acc.x);
            acc.y = fmaf(w.y, v01.y, acc.y);
            acc.z = fmaf(w.y, v01.z, acc.z);
            acc.w = fmaf(w.y, v01.w, acc.w);
            acc.x = fmaf(w.z, v10.x, acc.x);
            acc.y = fmaf(w.z, v10.y, acc.y);
            acc.z = fmaf(w.z, v10.z, acc.z);
            acc.w = fmaf(w.z, v10.w, acc.w);
            acc.x = fmaf(w.w, v11.x, acc.x);
            acc.y = fmaf(w.w, v11.y, acc.y);
            acc.z = fmaf(w.w, v11.z, acc.z);
            acc.w = fmaf(w.w, v11.w, acc.w);
        }

        *(float4*)&out[(size_t)row * 256 + c4 * 4] = acc;
    }
}

// ---------------------------------------------------------------------------
extern "C" void kernel_launch(void* const* d_in, const int* in_sizes, int n_in,
                              void* d_out, int out_size)
{
    const float* query = (const float*)d_in[0];   // (2, LEN_Q, 256)
    const float* ref   = (const float*)d_in[1];   // (2, LEN_Q, 4, 2)
    const float* value = (const float*)d_in[2];   // (2, LEN_Q, 256)
    const float* Woff  = (const float*)d_in[3];   // (256, 256)
    const float* boff  = (const float*)d_in[4];   // (256,)
    const float* Wattn = (const float*)d_in[5];   // (256, 128)
    const float* battn = (const float*)d_in[6];   // (128,)
    float* out = (float*)d_out;                   // (2, LEN_Q, 256)

    dim3 ggrid((NQ + 127) / 128, 3);
    msda_gemm_kernel<<<ggrid, 256>>>(query, Woff, boff, Wattn, battn);

    const int nblocks = (NQ + RB - 1) / RB;       // 1662
    msda_sample_kernel<<<nblocks, 256>>>(ref, value, out);
}

// round 7
// speedup vs baseline: 2.1940x; 1.1382x over previous
#include <cuda_runtime.h>
#include <cuda_fp16.h>

#define LEN_Q   13294
#define NQ      (2 * LEN_Q)     // 26588 rows (b*LEN_Q + q)
#define N_OUT   384             // 256 offset cols + 128 attn cols
#define RB      16              // rows per sampler block

// Scratch: projection output P[NQ][384]; fp16 copy of value
__device__ float  g_P[NQ * N_OUT];
__device__ __half g_Vh[(size_t)NQ * 256];

// ---------------------------------------------------------------------------
// tf32 / cp.async helpers
// ---------------------------------------------------------------------------
__device__ __forceinline__ unsigned f2tf32(float f) {
    unsigned u;
    asm("cvt.rna.tf32.f32 %0, %1;" : "=r"(u) : "f"(f));
    return u;
}
__device__ __forceinline__ void mma_tf32(float* d, const unsigned* a, const unsigned* b) {
    asm volatile(
        "mma.sync.aligned.m16n8k8.row.col.f32.tf32.tf32.f32 "
        "{%0,%1,%2,%3}, {%4,%5,%6,%7}, {%8,%9}, {%0,%1,%2,%3};"
        : "+f"(d[0]), "+f"(d[1]), "+f"(d[2]), "+f"(d[3])
        : "r"(a[0]), "r"(a[1]), "r"(a[2]), "r"(a[3]),
          "r"(b[0]), "r"(b[1]));
}
__device__ __forceinline__ unsigned smem_u32(const void* p) {
    return (unsigned)__cvta_generic_to_shared(p);
}
__device__ __forceinline__ void cp_async16(unsigned dst, const void* src, int src_bytes) {
    asm volatile("cp.async.ca.shared.global [%0], [%1], 16, %2;"
                 :: "r"(dst), "l"(src), "r"(src_bytes));
}
__device__ __forceinline__ void cp_commit() {
    asm volatile("cp.async.commit_group;");
}
template <int N>
__device__ __forceinline__ void cp_wait() {
    asm volatile("cp.async.wait_group %0;" :: "n"(N));
}

// ---------------------------------------------------------------------------
// value fp32 -> fp16 conversion (one float4 -> two half2 per thread)
// ---------------------------------------------------------------------------
__global__ __launch_bounds__(256) void msda_cvt_kernel(const float* __restrict__ v)
{
    const int i = blockIdx.x * 256 + threadIdx.x;       // float4 index
    const float4 f = ((const float4*)v)[i];
    __half2* dst = (__half2*)g_Vh + (size_t)i * 2;
    dst[0] = __floats2half2_rn(f.x, f.y);
    dst[1] = __floats2half2_rn(f.z, f.w);
}

// ---------------------------------------------------------------------------
// GEMM v4 (unchanged, 56.6us measured): tf32 mma.sync + cp.async double buffer.
// ---------------------------------------------------------------------------
#define LDA 20     // 16 + 4 pad (floats)
#define LDB 132    // 128 + 4 pad (floats)

__global__ __launch_bounds__(256) void msda_gemm_kernel(
    const float* __restrict__ Q,
    const float* __restrict__ Woff, const float* __restrict__ boff,
    const float* __restrict__ Wattn, const float* __restrict__ battn)
{
    __shared__ float As[2][128 * LDA];   // [m][k]
    __shared__ float Bs[2][16 * LDB];    // [k][n]

    const int m0   = blockIdx.x * 128;
    const int nblk = blockIdx.y;

    const float* W; const float* bias; int ldW, n0;
    if (nblk < 2) { W = Woff;  bias = boff + nblk * 128; ldW = 256; n0 = nblk * 128; }
    else          { W = Wattn; bias = battn;             ldW = 128; n0 = 0;          }
    const int outn0 = nblk * 128;

    const int tid  = threadIdx.x;
    const int wid  = tid >> 5;
    const int lane = tid & 31;
    const int g    = lane >> 2;
    const int tig  = lane & 3;
    const int wm   = wid & 1;
    const int wn   = wid >> 1;

    const int ac0r = tid >> 2,         ac0k = (tid & 3) * 4;
    const int ac1r = (tid + 256) >> 2, ac1k = ((tid + 256) & 3) * 4;
    const int bc0r = tid >> 5,         bc0c = (tid & 31) * 4;
    const int bc1r = (tid + 256) >> 5, bc1c = ((tid + 256) & 31) * 4;

    const unsigned sA[2] = { smem_u32(&As[0][0]), smem_u32(&As[1][0]) };
    const unsigned sB[2] = { smem_u32(&Bs[0][0]), smem_u32(&Bs[1][0]) };

    auto load_tile = [&](int s, int k0) {
        int v0 = (m0 + ac0r < NQ) ? 16 : 0;
        int v1 = (m0 + ac1r < NQ) ? 16 : 0;
        cp_async16(sA[s] + (ac0r * LDA + ac0k) * 4,
                   &Q[(size_t)(m0 + ac0r) * 256 + k0 + ac0k], v0);
        cp_async16(sA[s] + (ac1r * LDA + ac1k) * 4,
                   &Q[(size_t)(m0 + ac1r) * 256 + k0 + ac1k], v1);
        cp_async16(sB[s] + (bc0r * LDB + bc0c) * 4,
                   &W[(size_t)(k0 + bc0r) * ldW + n0 + bc0c], 16);
        cp_async16(sB[s] + (bc1r * LDB + bc1c) * 4,
                   &W[(size_t)(k0 + bc1r) * ldW + n0 + bc1c], 16);
        cp_commit();
    };

    float acc[4][4][4];
#pragma unroll
    for (int tm = 0; tm < 4; tm++)
#pragma unroll
        for (int tn = 0; tn < 4; tn++)
#pragma unroll
            for (int r = 0; r < 4; r++) acc[tm][tn][r] = 0.f;

    load_tile(0, 0);

#pragma unroll 1
    for (int it = 0; it < 16; it++) {
        const int s = it & 1;
        if (it + 1 < 16) {
            load_tile(1 - s, (it + 1) * 16);
            cp_wait<1>();
        } else {
            cp_wait<0>();
        }
        __syncthreads();

        const float* Ab = &As[s][0];
        const float* Bb = &Bs[s][0];
#pragma unroll
        for (int ks = 0; ks < 2; ks++) {
            const int kk = ks * 8;
            unsigned af[4][4];
#pragma unroll
            for (int tm = 0; tm < 4; tm++) {
                const int r = wm * 64 + tm * 16;
                af[tm][0] = f2tf32(Ab[(r + g)     * LDA + kk + tig]);
                af[tm][1] = f2tf32(Ab[(r + g + 8) * LDA + kk + tig]);
                af[tm][2] = f2tf32(Ab[(r + g)     * LDA + kk + tig + 4]);
                af[tm][3] = f2tf32(Ab[(r + g + 8) * LDA + kk + tig + 4]);
            }
            unsigned bf[4][2];
#pragma unroll
            for (int tn = 0; tn < 4; tn++) {
                const int c = wn * 32 + tn * 8;
                bf[tn][0] = f2tf32(Bb[(kk + tig)     * LDB + c + g]);
                bf[tn][1] = f2tf32(Bb[(kk + tig + 4) * LDB + c + g]);
            }
#pragma unroll
            for (int tm = 0; tm < 4; tm++)
#pragma unroll
                for (int tn = 0; tn < 4; tn++)
                    mma_tf32(acc[tm][tn], af[tm], bf[tn]);
        }
        __syncthreads();
    }

#pragma unroll
    for (int tn = 0; tn < 4; tn++) {
        const int cl = wn * 32 + tn * 8 + tig * 2;
        const float2 bv = *(const float2*)&bias[cl];
#pragma unroll
        for (int tm = 0; tm < 4; tm++) {
            const int r0 = m0 + wm * 64 + tm * 16 + g;
            const int r1 = r0 + 8;
            if (r0 < NQ) {
                float2 o = make_float2(acc[tm][tn][0] + bv.x, acc[tm][tn][1] + bv.y);
                *(float2*)&g_P[(size_t)r0 * N_OUT + outn0 + cl] = o;
            }
            if (r1 < NQ) {
                float2 o = make_float2(acc[tm][tn][2] + bv.x, acc[tm][tn][3] + bv.y);
                *(float2*)&g_P[(size_t)r1 * N_OUT + outn0 + cl] = o;
            }
        }
    }
}

// ---------------------------------------------------------------------------
// Sampling v4: same two-phase structure as R4 (111us), but phase 2 gathers
// from the fp16 value copy: 8 B per lane per corner (LDG.64), fp32 accum.
// Halves L1/L2 sector traffic of the dominant loop.
// ---------------------------------------------------------------------------
__global__ __launch_bounds__(256) void msda_sample_kernel(
    const float* __restrict__ ref,    // (2, LEN_Q, 4, 2)
    float* __restrict__ out)          // (2, LEN_Q, 256)
{
    __shared__ float4 s_w[RB][8][17];   // padded: head stride 17
    __shared__ int    s_i[RB][8][17];

    const int row0 = blockIdx.x * RB;
    const int t    = threadIdx.x;

    // ---------------- Phase 1 (unchanged) ----------------
    {
        const int gq   = t >> 1;
        const int half = t & 1;
        const int rl   = gq >> 3;
        const int h    = gq & 7;
        const int row  = row0 + rl;

        if (row < NQ) {
            const float* Prow = g_P + (size_t)row * N_OUT;

            float lg[16];
#pragma unroll
            for (int v = 0; v < 4; v++) {
                float4 q = *(const float4*)&Prow[256 + h * 16 + v * 4];
                lg[v*4+0] = q.x; lg[v*4+1] = q.y; lg[v*4+2] = q.z; lg[v*4+3] = q.w;
            }
            float mx = lg[0];
#pragma unroll
            for (int v = 1; v < 16; v++) mx = fmaxf(mx, lg[v]);
            float ssum = 0.f;
#pragma unroll
            for (int v = 0; v < 16; v++) ssum += __expf(lg[v] - mx);
            const float inv = 1.f / ssum;

#pragma unroll
            for (int jj = 0; jj < 8; jj++) {
                const int j = half * 8 + jj;
                const int l = j >> 2;
                const int D = (l == 0) ? 100 : (l == 1) ? 50 : (l == 2) ? 25 : 13;

                const float wgt  = __expf(lg[j] - mx) * inv;
                const float offx = Prow[h * 32 + j * 2];
                const float offy = Prow[h * 32 + j * 2 + 1];
                const float rx = ref[(size_t)(row * 4 + l) * 2 + 0];
                const float ry = ref[(size_t)(row * 4 + l) * 2 + 1];
                const float x = fmaf(rx, (float)D, offx) - 0.5f;
                const float y = fmaf(ry, (float)D, offy) - 0.5f;

                const float xf = floorf(x), yf = floorf(y);
                const int x0 = (int)xf, y0 = (int)yf;
                const float fx = x - xf, fy = y - yf;

                const float gx0 = (x0 >= 0     && x0 < D)     ? (1.f - fx) : 0.f;
                const float gx1 = (x0 + 1 >= 0 && x0 + 1 < D) ? fx         : 0.f;
                const float gy0 = (y0 >= 0     && y0 < D)     ? (1.f - fy) : 0.f;
                const float gy1 = (y0 + 1 >= 0 && y0 + 1 < D) ? fy         : 0.f;

                const int cx = min(max(x0, 0), D - 2);
                const int cy = min(max(y0, 0), D - 2);
                const float wl = (x0 < 0) ? gx1 : ((x0 <= D - 2) ? gx0 : 0.f);
                const float wr = (x0 < 0) ? 0.f : ((x0 <= D - 2) ? gx1 : gx0);
                const float wt = (y0 < 0) ? gy1 : ((y0 <= D - 2) ? gy0 : 0.f);
                const float wb = (y0 < 0) ? 0.f : ((y0 <= D - 2) ? gy1 : gy0);

                s_w[rl][h][j] = make_float4(wgt * wl * wt, wgt * wr * wt,
                                            wgt * wl * wb, wgt * wr * wb);
                s_i[rl][h][j] = cy * D + cx;
            }
        }
    }
    __syncthreads();

    // ---------------- Phase 2 (fp16 gathers) ----------------
#pragma unroll
    for (int it = 0; it < 4; it++) {
        const int T   = it * 256 + t;
        const int rl  = T >> 6;
        const int c4  = T & 63;              // float4 slot: head = c4>>3
        const int row = row0 + rl;
        if (row >= NQ) continue;

        const int h = c4 >> 3;
        const int b = (row >= LEN_Q) ? 1 : 0;
        const __half* vb = g_Vh + (size_t)b * LEN_Q * 256 + h * 32 + (c4 & 7) * 4;

        float4 acc = make_float4(0.f, 0.f, 0.f, 0.f);
#pragma unroll
        for (int j = 0; j < 16; j++) {
            const int l    = j >> 2;                          // compile-time
            const int DD   = (l == 0) ? 100 : (l == 1) ? 50 : (l == 2) ? 25 : 13;
            const int BASE = (l == 0) ? 0 : (l == 1) ? 10000 : (l == 2) ? 12500 : 13125;

            const float4 w  = s_w[rl][h][j];
            const int    ix = s_i[rl][h][j];
            const __half* p = vb + (size_t)(BASE + ix) * 256;

            const uint2 u00 = *(const uint2*)p;
            const uint2 u01 = *(const uint2*)(p + 256);
            const uint2 u10 = *(const uint2*)(p + DD * 256);
            const uint2 u11 = *(const uint2*)(p + DD * 256 + 256);

            const float2 a00 = __half22float2(*(const __half2*)&u00.x);
            const float2 b00 = __half22float2(*(const __half2*)&u00.y);
            const float2 a01 = __half22float2(*(const __half2*)&u01.x);
            const float2 b01 = __half22float2(*(const __half2*)&u01.y);
            const float2 a10 = __half22float2(*(const __half2*)&u10.x);
            const float2 b10 = __half22float2(*(const __half2*)&u10.y);
            const float2 a11 = __half22float2(*(const __half2*)&u11.x);
            const float2 b11 = __half22float2(*(const __half2*)&u11.y);

            acc.x = fmaf(w.x, a00.x, acc.x);
            acc.y = fmaf(w.x, a00.y, acc.y);
            acc.z = fmaf(w.x, b00.x, acc.z);
            acc.w = fmaf(w.x, b00.y, acc.w);
            acc.x = fmaf(w.y, a01.x, acc.x);
            acc.y = fmaf(w.y, a01.y, acc.y);
            acc.z = fmaf(w.y, b01.x, acc.z);
            acc.w = fmaf(w.y, b01.y, acc.w);
            acc.x = fmaf(w.z, a10.x, acc.x);
            acc.y = fmaf(w.z, a10.y, acc.y);
            acc.z = fmaf(w.z, b10.x, acc.z);
            acc.w = fmaf(w.z, b10.y, acc.w);
            acc.x = fmaf(w.w, a11.x, acc.x);
            acc.y = fmaf(w.w, a11.y, acc.y);
            acc.z = fmaf(w.w, b11.x, acc.z);
            acc.w = fmaf(w.w, b11.y, acc.w);
        }

        *(float4*)&out[(size_t)row * 256 + c4 * 4] = acc;
    }
}

// ---------------------------------------------------------------------------
extern "C" void kernel_launch(void* const* d_in, const int* in_sizes, int n_in,
                              void* d_out, int out_size)
{
    const float* query = (const float*)d_in[0];   // (2, LEN_Q, 256)
    const float* ref   = (const float*)d_in[1];   // (2, LEN_Q, 4, 2)
    const float* value = (const float*)d_in[2];   // (2, LEN_Q, 256)
    const float* Woff  = (const float*)d_in[3];   // (256, 256)
    const float* boff  = (const float*)d_in[4];   // (256,)
    const float* Wattn = (const float*)d_in[5];   // (256, 128)
    const float* battn = (const float*)d_in[6];   // (128,)
    float* out = (float*)d_out;                   // (2, LEN_Q, 256)

    // value -> fp16 copy (NQ*256/4 float4s, 6647 blocks exactly)
    msda_cvt_kernel<<<(NQ * 256 / 4 + 255) / 256, 256>>>(value);

    dim3 ggrid((NQ + 127) / 128, 3);
    msda_gemm_kernel<<<ggrid, 256>>>(query, Woff, boff, Wattn, battn);

    const int nblocks = (NQ + RB - 1) / RB;       // 1662
    msda_sample_kernel<<<nblocks, 256>>>(ref, out);
}

// round 9
// speedup vs baseline: 2.2551x; 1.0279x over previous
#include <cuda_runtime.h>
#include <cuda_fp16.h>

#define LEN_Q   13294
#define NQ      (2 * LEN_Q)     // 26588 rows (b*LEN_Q + q)
#define N_OUT   384             // 256 offset cols + 128 attn cols
#define RB      8               // rows per sampler block (512 threads)
#define GEMM_MBLKS 208          // ceil(NQ/128)
#define GEMM_BLOCKS (GEMM_MBLKS * 3)
#define CVT_BLOCKS  (NQ * 256 / 4 / 256)   // 6647 exactly

// Scratch: projection output P[NQ][384]; fp16 copy of value
__device__ float  g_P[NQ * N_OUT];
__device__ __half g_Vh[(size_t)NQ * 256];

// ---------------------------------------------------------------------------
// tf32 / cp.async helpers
// ---------------------------------------------------------------------------
__device__ __forceinline__ unsigned f2tf32(float f) {
    unsigned u;
    asm("cvt.rna.tf32.f32 %0, %1;" : "=r"(u) : "f"(f));
    return u;
}
__device__ __forceinline__ void mma_tf32(float* d, const unsigned* a, const unsigned* b) {
    asm volatile(
        "mma.sync.aligned.m16n8k8.row.col.f32.tf32.tf32.f32 "
        "{%0,%1,%2,%3}, {%4,%5,%6,%7}, {%8,%9}, {%0,%1,%2,%3};"
        : "+f"(d[0]), "+f"(d[1]), "+f"(d[2]), "+f"(d[3])
        : "r"(a[0]), "r"(a[1]), "r"(a[2]), "r"(a[3]),
          "r"(b[0]), "r"(b[1]));
}
__device__ __forceinline__ unsigned smem_u32(const void* p) {
    return (unsigned)__cvta_generic_to_shared(p);
}
__device__ __forceinline__ void cp_async16(unsigned dst, const void* src, int src_bytes) {
    asm volatile("cp.async.ca.shared.global [%0], [%1], 16, %2;"
                 :: "r"(dst), "l"(src), "r"(src_bytes));
}
__device__ __forceinline__ void cp_commit() {
    asm volatile("cp.async.commit_group;");
}
template <int N>
__device__ __forceinline__ void cp_wait() {
    asm volatile("cp.async.wait_group %0;" :: "n"(N));
}

// ---------------------------------------------------------------------------
// Fused kernel: blocks [0, GEMM_BLOCKS) run the tf32 GEMM (56.6us path,
// unchanged); blocks [GEMM_BLOCKS, +CVT_BLOCKS) convert value fp32->fp16.
// The cvt work rides the GEMM's partial waves instead of a serial 8.7us.
// ---------------------------------------------------------------------------
#define LDA 20     // 16 + 4 pad (floats)
#define LDB 132    // 128 + 4 pad (floats)

__global__ __launch_bounds__(256) void msda_gemm_cvt_kernel(
    const float* __restrict__ Q,
    const float* __restrict__ Woff, const float* __restrict__ boff,
    const float* __restrict__ Wattn, const float* __restrict__ battn,
    const float* __restrict__ value)
{
    // ---- cvt part -----------------------------------------------------
    if (blockIdx.x >= GEMM_BLOCKS) {
        const int i = (blockIdx.x - GEMM_BLOCKS) * 256 + threadIdx.x;  // float4 idx
        const float4 f = ((const float4*)value)[i];
        __half2* dst = (__half2*)g_Vh + (size_t)i * 2;
        dst[0] = __floats2half2_rn(f.x, f.y);
        dst[1] = __floats2half2_rn(f.z, f.w);
        return;
    }

    // ---- GEMM part ----------------------------------------------------
    __shared__ float As[2][128 * LDA];   // [m][k]
    __shared__ float Bs[2][16 * LDB];    // [k][n]

    const int mblk = blockIdx.x % GEMM_MBLKS;
    const int nblk = blockIdx.x / GEMM_MBLKS;
    const int m0   = mblk * 128;

    const float* W; const float* bias; int ldW, n0;
    if (nblk < 2) { W = Woff;  bias = boff + nblk * 128; ldW = 256; n0 = nblk * 128; }
    else          { W = Wattn; bias = battn;             ldW = 128; n0 = 0;          }
    const int outn0 = nblk * 128;

    const int tid  = threadIdx.x;
    const int wid  = tid >> 5;
    const int lane = tid & 31;
    const int g    = lane >> 2;
    const int tig  = lane & 3;
    const int wm   = wid & 1;
    const int wn   = wid >> 1;

    const int ac0r = tid >> 2,         ac0k = (tid & 3) * 4;
    const int ac1r = (tid + 256) >> 2, ac1k = ((tid + 256) & 3) * 4;
    const int bc0r = tid >> 5,         bc0c = (tid & 31) * 4;
    const int bc1r = (tid + 256) >> 5, bc1c = ((tid + 256) & 31) * 4;

    const unsigned sA[2] = { smem_u32(&As[0][0]), smem_u32(&As[1][0]) };
    const unsigned sB[2] = { smem_u32(&Bs[0][0]), smem_u32(&Bs[1][0]) };

    auto load_tile = [&](int s, int k0) {
        int v0 = (m0 + ac0r < NQ) ? 16 : 0;
        int v1 = (m0 + ac1r < NQ) ? 16 : 0;
        cp_async16(sA[s] + (ac0r * LDA + ac0k) * 4,
                   &Q[(size_t)(m0 + ac0r) * 256 + k0 + ac0k], v0);
        cp_async16(sA[s] + (ac1r * LDA + ac1k) * 4,
                   &Q[(size_t)(m0 + ac1r) * 256 + k0 + ac1k], v1);
        cp_async16(sB[s] + (bc0r * LDB + bc0c) * 4,
                   &W[(size_t)(k0 + bc0r) * ldW + n0 + bc0c], 16);
        cp_async16(sB[s] + (bc1r * LDB + bc1c) * 4,
                   &W[(size_t)(k0 + bc1r) * ldW + n0 + bc1c], 16);
        cp_commit();
    };

    float acc[4][4][4];
#pragma unroll
    for (int tm = 0; tm < 4; tm++)
#pragma unroll
        for (int tn = 0; tn < 4; tn++)
#pragma unroll
            for (int r = 0; r < 4; r++) acc[tm][tn][r] = 0.f;

    load_tile(0, 0);

#pragma unroll 1
    for (int it = 0; it < 16; it++) {
        const int s = it & 1;
        if (it + 1 < 16) {
            load_tile(1 - s, (it + 1) * 16);
            cp_wait<1>();
        } else {
            cp_wait<0>();
        }
        __syncthreads();

        const float* Ab = &As[s][0];
        const float* Bb = &Bs[s][0];
#pragma unroll
        for (int ks = 0; ks < 2; ks++) {
            const int kk = ks * 8;
            unsigned af[4][4];
#pragma unroll
            for (int tm = 0; tm < 4; tm++) {
                const int r = wm * 64 + tm * 16;
                af[tm][0] = f2tf32(Ab[(r + g)     * LDA + kk + tig]);
                af[tm][1] = f2tf32(Ab[(r + g + 8) * LDA + kk + tig]);
                af[tm][2] = f2tf32(Ab[(r + g)     * LDA + kk + tig + 4]);
                af[tm][3] = f2tf32(Ab[(r + g + 8) * LDA + kk + tig + 4]);
            }
            unsigned bf[4][2];
#pragma unroll
            for (int tn = 0; tn < 4; tn++) {
                const int c = wn * 32 + tn * 8;
                bf[tn][0] = f2tf32(Bb[(kk + tig)     * LDB + c + g]);
                bf[tn][1] = f2tf32(Bb[(kk + tig + 4) * LDB + c + g]);
            }
#pragma unroll
            for (int tm = 0; tm < 4; tm++)
#pragma unroll
                for (int tn = 0; tn < 4; tn++)
                    mma_tf32(acc[tm][tn], af[tm], bf[tn]);
        }
        __syncthreads();
    }

#pragma unroll
    for (int tn = 0; tn < 4; tn++) {
        const int cl = wn * 32 + tn * 8 + tig * 2;
        const float2 bv = *(const float2*)&bias[cl];
#pragma unroll
        for (int tm = 0; tm < 4; tm++) {
            const int r0 = m0 + wm * 64 + tm * 16 + g;
            const int r1 = r0 + 8;
            if (r0 < NQ) {
                float2 o = make_float2(acc[tm][tn][0] + bv.x, acc[tm][tn][1] + bv.y);
                *(float2*)&g_P[(size_t)r0 * N_OUT + outn0 + cl] = o;
            }
            if (r1 < NQ) {
                float2 o = make_float2(acc[tm][tn][2] + bv.x, acc[tm][tn][3] + bv.y);
                *(float2*)&g_P[(size_t)r1 * N_OUT + outn0 + cl] = o;
            }
        }
    }
}

// ---------------------------------------------------------------------------
// Sampling v5: 512 threads, RB=8 rows per block, no serial row loop in
// phase 2 (each thread = exactly one float4-slot). smem 22KB. fp16 gathers.
// ---------------------------------------------------------------------------
__global__ __launch_bounds__(512) void msda_sample_kernel(
    const float* __restrict__ ref,    // (2, LEN_Q, 4, 2)
    float* __restrict__ out)          // (2, LEN_Q, 256)
{
    __shared__ float4 s_w[RB][8][17];   // padded: head stride 17
    __shared__ int    s_i[RB][8][17];

    const int row0 = blockIdx.x * RB;
    const int t    = threadIdx.x;

    // ---------------- Phase 1: 8 threads per (row, head), 2 points each ----
    {
        const int pair = t >> 3;        // 0..63: (row_local, head)
        const int sub  = t & 7;         // 2 points each
        const int rl   = pair >> 3;
        const int h    = pair & 7;
        const int row  = row0 + rl;

        if (row < NQ) {
            const float* Prow = g_P + (size_t)row * N_OUT;

            float lg[16];
#pragma unroll
            for (int v = 0; v < 4; v++) {
                float4 q = *(const float4*)&Prow[256 + h * 16 + v * 4];
                lg[v*4+0] = q.x; lg[v*4+1] = q.y; lg[v*4+2] = q.z; lg[v*4+3] = q.w;
            }
            float mx = lg[0];
#pragma unroll
            for (int v = 1; v < 16; v++) mx = fmaxf(mx, lg[v]);
            float ssum = 0.f;
#pragma unroll
            for (int v = 0; v < 16; v++) ssum += __expf(lg[v] - mx);
            const float inv = 1.f / ssum;

#pragma unroll
            for (int jj = 0; jj < 2; jj++) {
                const int j = sub * 2 + jj;
                const int l = j >> 2;
                const int D = (l == 0) ? 100 : (l == 1) ? 50 : (l == 2) ? 25 : 13;

                const float wgt  = __expf(lg[j] - mx) * inv;
                const float offx = Prow[h * 32 + j * 2];
                const float offy = Prow[h * 32 + j * 2 + 1];
                const float rx = ref[(size_t)(row * 4 + l) * 2 + 0];
                const float ry = ref[(size_t)(row * 4 + l) * 2 + 1];
                const float x = fmaf(rx, (float)D, offx) - 0.5f;
                const float y = fmaf(ry, (float)D, offy) - 0.5f;

                const float xf = floorf(x), yf = floorf(y);
                const int x0 = (int)xf, y0 = (int)yf;
                const float fx = x - xf, fy = y - yf;

                const float gx0 = (x0 >= 0     && x0 < D)     ? (1.f - fx) : 0.f;
                const float gx1 = (x0 + 1 >= 0 && x0 + 1 < D) ? fx         : 0.f;
                const float gy0 = (y0 >= 0     && y0 < D)     ? (1.f - fy) : 0.f;
                const float gy1 = (y0 + 1 >= 0 && y0 + 1 < D) ? fy         : 0.f;

                const int cx = min(max(x0, 0), D - 2);
                const int cy = min(max(y0, 0), D - 2);
                const float wl = (x0 < 0) ? gx1 : ((x0 <= D - 2) ? gx0 : 0.f);
                const float wr = (x0 < 0) ? 0.f : ((x0 <= D - 2) ? gx1 : gx0);
                const float wt = (y0 < 0) ? gy1 : ((y0 <= D - 2) ? gy0 : 0.f);
                const float wb = (y0 < 0) ? 0.f : ((y0 <= D - 2) ? gy1 : gy0);

                s_w[rl][h][j] = make_float4(wgt * wl * wt, wgt * wr * wt,
                                            wgt * wl * wb, wgt * wr * wb);
                s_i[rl][h][j] = cy * D + cx;
            }
        }
    }
    __syncthreads();

    // ---------------- Phase 2: one float4-slot per thread ----------------
    {
        const int rl  = t >> 6;              // 0..7
        const int c4  = t & 63;              // float4 slot: head = c4>>3
        const int row = row0 + rl;
        if (row >= NQ) return;

        const int h = c4 >> 3;
        const int b = (row >= LEN_Q) ? 1 : 0;
        const __half* vb = g_Vh + (size_t)b * LEN_Q * 256 + h * 32 + (c4 & 7) * 4;

        float4 acc = make_float4(0.f, 0.f, 0.f, 0.f);
#pragma unroll
        for (int j = 0; j < 16; j++) {
            const int l    = j >> 2;                          // compile-time
            const int DD   = (l == 0) ? 100 : (l == 1) ? 50 : (l == 2) ? 25 : 13;
            const int BASE = (l == 0) ? 0 : (l == 1) ? 10000 : (l == 2) ? 12500 : 13125;

            const float4 w  = s_w[rl][h][j];
            const int    ix = s_i[rl][h][j];
            const __half* p = vb + (size_t)(BASE + ix) * 256;

            const uint2 u00 = *(const uint2*)p;
            const uint2 u01 = *(const uint2*)(p + 256);
            const uint2 u10 = *(const uint2*)(p + DD * 256);
            const uint2 u11 = *(const uint2*)(p + DD * 256 + 256);

            const float2 a00 = __half22float2(*(const __half2*)&u00.x);
            const float2 b00 = __half22float2(*(const __half2*)&u00.y);
            const float2 a01 = __half22float2(*(const __half2*)&u01.x);
            const float2 b01 = __half22float2(*(const __half2*)&u01.y);
            const float2 a10 = __half22float2(*(const __half2*)&u10.x);
            const float2 b10 = __half22float2(*(const __half2*)&u10.y);
            const float2 a11 = __half22float2(*(const __half2*)&u11.x);
            const float2 b11 = __half22float2(*(const __half2*)&u11.y);

            acc.x = fmaf(w.x, a00.x, acc.x);
            acc.y = fmaf(w.x, a00.y, acc.y);
            acc.z = fmaf(w.x, b00.x, acc.z);
            acc.w = fmaf(w.x, b00.y, acc.w);
            acc.x = fmaf(w.y, a01.x, acc.x);
            acc.y = fmaf(w.y, a01.y, acc.y);
            acc.z = fmaf(w.y, b01.x, acc.z);
            acc.w = fmaf(w.y, b01.y, acc.w);
            acc.x = fmaf(w.z, a10.x, acc.x);
            acc.y = fmaf(w.z, a10.y, acc.y);
            acc.z = fmaf(w.z, b10.x, acc.z);
            acc.w = fmaf(w.z, b10.y, acc.w);
            acc.x = fmaf(w.w, a11.x, acc.x);
            acc.y = fmaf(w.w, a11.y, acc.y);
            acc.z = fmaf(w.w, b11.x, acc.z);
            acc.w = fmaf(w.w, b11.y, acc.w);
        }

        *(float4*)&out[(size_t)row * 256 + c4 * 4] = acc;
    }
}

// ---------------------------------------------------------------------------
extern "C" void kernel_launch(void* const* d_in, const int* in_sizes, int n_in,
                              void* d_out, int out_size)
{
    const float* query = (const float*)d_in[0];   // (2, LEN_Q, 256)
    const float* ref   = (const float*)d_in[1];   // (2, LEN_Q, 4, 2)
    const float* value = (const float*)d_in[2];   // (2, LEN_Q, 256)
    const float* Woff  = (const float*)d_in[3];   // (256, 256)
    const float* boff  = (const float*)d_in[4];   // (256,)
    const float* Wattn = (const float*)d_in[5];   // (256, 128)
    const float* battn = (const float*)d_in[6];   // (128,)
    float* out = (float*)d_out;                   // (2, LEN_Q, 256)

    msda_gemm_cvt_kernel<<<GEMM_BLOCKS + CVT_BLOCKS, 256>>>(
        query, Woff, boff, Wattn, battn, value);

    const int nblocks = (NQ + RB - 1) / RB;       // 3324
    msda_sample_kernel<<<nblocks, 512>>>(ref, out);
}